// round 1
// baseline (speedup 1.0000x reference)
#include <cuda_runtime.h>

#define Dd  512
#define Sd  512
#define Bd  2
#define Hd  8
#define HDd 64

// ---------------- scratch (device globals; no allocs allowed) ----------------
__device__ float g_Wq[Dd * Dd];      // Wq folded with Aq (per-head block)
__device__ float g_Wk[Dd * Dd];      // Wk folded with Ak
__device__ float g_bq[Dd];
__device__ float g_bk[Dd];
__device__ float g_qt[Bd * Sd * Dd]; // q_term, [B*S, D] with head-column blocks
__device__ float g_kt[Bd * Sd * Dd]; // k_term
__device__ float g_v [Bd * Sd * Dd]; // v projection
__device__ float g_ctx[Bd * Sd * Dd];

__device__ __forceinline__ float tanh_fast(float x) {
    float y;
    asm("tanh.approx.f32 %0, %1;" : "=f"(y) : "f"(x));
    return y;
}

// ---------------- fold kernel: Wd[r, h*64+c] = sum_j W[r, h*64+j] * A[j,c] ----
// sel==0 -> (g_Wq, g_bq), sel==1 -> (g_Wk, g_bk)
__global__ void fold_kernel(const float* __restrict__ W,
                            const float* __restrict__ A,
                            const float* __restrict__ bsrc,
                            int sel) {
    __shared__ float As[64 * 64];
    __shared__ float ws[64];
    int r = blockIdx.x, h = blockIdx.y, c = threadIdx.x;
    float* Wd = sel ? g_Wk : g_Wq;
    float* bd = sel ? g_bk : g_bq;

    for (int i = c; i < 64 * 64; i += 64) As[i] = A[i];
    ws[c] = W[r * Dd + h * 64 + c];
    __syncthreads();

    float acc = 0.f;
    #pragma unroll 16
    for (int j = 0; j < 64; j++) acc += ws[j] * As[j * 64 + c];
    Wd[r * Dd + h * 64 + c] = acc;

    if (r == 0) {
        float bacc = 0.f;
        #pragma unroll 16
        for (int j = 0; j < 64; j++) bacc += bsrc[h * 64 + j] * As[j * 64 + c];
        bd[h * 64 + c] = bacc;
    }
}

// ---------------- generic 64x64 fp32 GEMM tile: C = A[1024,512] @ W[512,512] + bias
__device__ __forceinline__ void gemm_body(const float* __restrict__ A,
                                          const float* __restrict__ W,
                                          const float* __restrict__ bias,
                                          float* __restrict__ C) {
    __shared__ float As[16][64];  // transposed A tile
    __shared__ float Ws[16][64];
    int m0 = blockIdx.y * 64, n0 = blockIdx.x * 64;
    int tid = threadIdx.x;
    int tx = tid & 15, ty = tid >> 4;

    float acc[4][4] = {};

    for (int k0 = 0; k0 < Dd; k0 += 16) {
        {
            int r  = tid >> 2;
            int c4 = (tid & 3) << 2;
            float4 a = *(const float4*)(A + (size_t)(m0 + r) * Dd + k0 + c4);
            As[c4 + 0][r] = a.x; As[c4 + 1][r] = a.y;
            As[c4 + 2][r] = a.z; As[c4 + 3][r] = a.w;
            int rw = tid >> 4, cw = (tid & 15) << 2;
            *(float4*)&Ws[rw][cw] = *(const float4*)(W + (size_t)(k0 + rw) * Dd + n0 + cw);
        }
        __syncthreads();
        #pragma unroll
        for (int k = 0; k < 16; k++) {
            float4 a4 = *(const float4*)&As[k][ty << 2];
            float4 b4 = *(const float4*)&Ws[k][tx << 2];
            acc[0][0] += a4.x * b4.x; acc[0][1] += a4.x * b4.y;
            acc[0][2] += a4.x * b4.z; acc[0][3] += a4.x * b4.w;
            acc[1][0] += a4.y * b4.x; acc[1][1] += a4.y * b4.y;
            acc[1][2] += a4.y * b4.z; acc[1][3] += a4.y * b4.w;
            acc[2][0] += a4.z * b4.x; acc[2][1] += a4.z * b4.y;
            acc[2][2] += a4.z * b4.z; acc[2][3] += a4.z * b4.w;
            acc[3][0] += a4.w * b4.x; acc[3][1] += a4.w * b4.y;
            acc[3][2] += a4.w * b4.z; acc[3][3] += a4.w * b4.w;
        }
        __syncthreads();
    }

    float4 bb = *(const float4*)(bias + n0 + (tx << 2));
    #pragma unroll
    for (int i = 0; i < 4; i++) {
        float4 o;
        o.x = acc[i][0] + bb.x; o.y = acc[i][1] + bb.y;
        o.z = acc[i][2] + bb.z; o.w = acc[i][3] + bb.w;
        *(float4*)(C + (size_t)(m0 + (ty << 2) + i) * Dd + n0 + (tx << 2)) = o;
    }
}

__global__ __launch_bounds__(256) void gemm_qkv_kernel(const float* __restrict__ qin,
                                                       const float* __restrict__ kin,
                                                       const float* __restrict__ vin,
                                                       const float* __restrict__ Wv,
                                                       const float* __restrict__ bv) {
    const float *A, *W, *bias;
    float* C;
    if (blockIdx.z == 0)      { A = qin; W = g_Wq; bias = g_bq; C = g_qt; }
    else if (blockIdx.z == 1) { A = kin; W = g_Wk; bias = g_bk; C = g_kt; }
    else                      { A = vin; W = Wv;   bias = bv;   C = g_v;  }
    gemm_body(A, W, bias, C);
}

__global__ __launch_bounds__(256) void gemm_out_kernel(const float* __restrict__ Wo,
                                                       const float* __restrict__ bo,
                                                       float* __restrict__ out) {
    gemm_body(g_ctx, Wo, bo, out);
}

// ---------------- fused scores + softmax + ctx, one (b,h,q-tile) per block ----
#define TQ 16
#define CK 32

__global__ __launch_bounds__(256, 2) void attn_kernel(const float* __restrict__ av,
                                                      float* __restrict__ attn_out) {
    __shared__ float sc[TQ][Sd];       // 32 KB
    __shared__ float ks[CK][68];       // padded k-term chunk (8.5 KB)
    __shared__ float avs[64];

    int b = blockIdx.z, h = blockIdx.y;
    int q0 = blockIdx.x * TQ;
    int tid = threadIdx.x;
    int q = tid >> 4, lane = tid & 15;

    if (tid < 64) avs[tid] = av[tid];

    // this thread's q_term row -> registers
    float qreg[64];
    const float* qrow = g_qt + ((size_t)(b * Sd + q0 + q)) * Dd + h * HDd;
    #pragma unroll
    for (int d4 = 0; d4 < 64; d4 += 4) {
        float4 t = *(const float4*)(qrow + d4);
        qreg[d4] = t.x; qreg[d4 + 1] = t.y; qreg[d4 + 2] = t.z; qreg[d4 + 3] = t.w;
    }
    __syncthreads();

    // -------- scores: tanh(q_term + k_term) . av --------
    for (int c0 = 0; c0 < Sd; c0 += CK) {
        #pragma unroll
        for (int i = tid; i < CK * 16; i += 256) {   // float4-granular copy
            int kk = i >> 4, d4 = (i & 15) << 2;
            float4 t = *(const float4*)(g_kt + ((size_t)(b * Sd + c0 + kk)) * Dd + h * HDd + d4);
            *(float4*)&ks[kk][d4] = t;
        }
        __syncthreads();
        #pragma unroll
        for (int j = 0; j < CK / 16; j++) {
            int kk = lane + 16 * j;
            float acc = 0.f;
            #pragma unroll
            for (int d = 0; d < 64; d += 4) {
                float4 kv = *(const float4*)&ks[kk][d];
                float4 a  = *(const float4*)&avs[d];
                acc += tanh_fast(qreg[d + 0] + kv.x) * a.x;
                acc += tanh_fast(qreg[d + 1] + kv.y) * a.y;
                acc += tanh_fast(qreg[d + 2] + kv.z) * a.z;
                acc += tanh_fast(qreg[d + 3] + kv.w) * a.w;
            }
            sc[q][c0 + kk] = acc;
        }
        __syncthreads();
    }

    // -------- softmax per q row (warp per row, 2 rows/warp) --------
    int w = tid >> 5, ln = tid & 31;
    for (int qq = w; qq < TQ; qq += 8) {
        float mx = -1e30f;
        for (int k = ln; k < Sd; k += 32) mx = fmaxf(mx, sc[qq][k]);
        #pragma unroll
        for (int o = 16; o > 0; o >>= 1) mx = fmaxf(mx, __shfl_xor_sync(0xffffffffu, mx, o));
        float sum = 0.f;
        for (int k = ln; k < Sd; k += 32) {
            float e = __expf(sc[qq][k] - mx);
            sc[qq][k] = e;
            sum += e;
        }
        #pragma unroll
        for (int o = 16; o > 0; o >>= 1) sum += __shfl_xor_sync(0xffffffffu, sum, o);
        float inv = 1.f / sum;
        float* arow = attn_out + (((size_t)(b * Hd + h) * Sd) + q0 + qq) * Sd;
        for (int k = ln; k < Sd; k += 32) {
            float a = sc[qq][k] * inv;
            sc[qq][k] = a;
            arow[k] = a;
        }
    }
    __syncthreads();

    // -------- ctx = attn @ v (head slice) --------
    int dd = tid & 63, qg = tid >> 6;  // qg in 0..3, each owns 4 q rows
    float c[4] = {0.f, 0.f, 0.f, 0.f};
    const float* vcol = g_v + (size_t)b * Sd * Dd + h * HDd + dd;
    for (int k = 0; k < Sd; k += 4) {
        float v0 = vcol[(size_t)(k + 0) * Dd];
        float v1 = vcol[(size_t)(k + 1) * Dd];
        float v2 = vcol[(size_t)(k + 2) * Dd];
        float v3 = vcol[(size_t)(k + 3) * Dd];
        #pragma unroll
        for (int i = 0; i < 4; i++) {
            float4 a = *(const float4*)&sc[qg * 4 + i][k];
            c[i] += a.x * v0 + a.y * v1 + a.z * v2 + a.w * v3;
        }
    }
    #pragma unroll
    for (int i = 0; i < 4; i++)
        g_ctx[((size_t)(b * Sd) + q0 + qg * 4 + i) * Dd + h * HDd + dd] = c[i];
}

// ---------------- launch ----------------
extern "C" void kernel_launch(void* const* d_in, const int* in_sizes, int n_in,
                              void* d_out, int out_size) {
    const float* query = (const float*)d_in[0];
    const float* key_  = (const float*)d_in[1];
    const float* value = (const float*)d_in[2];
    const float* Wq    = (const float*)d_in[3];
    const float* bq    = (const float*)d_in[4];
    const float* Wk    = (const float*)d_in[5];
    const float* bk    = (const float*)d_in[6];
    const float* Wv    = (const float*)d_in[7];
    const float* bv    = (const float*)d_in[8];
    const float* Wo    = (const float*)d_in[9];
    const float* bo    = (const float*)d_in[10];
    const float* Aq    = (const float*)d_in[11];
    const float* Ak    = (const float*)d_in[12];
    const float* av    = (const float*)d_in[13];

    float* out      = (float*)d_out;                    // [B,S,D] = 524288 floats
    float* attn_out = out + (size_t)Bd * Sd * Dd;       // [B,H,S,S] = 4194304 floats

    fold_kernel<<<dim3(512, 8), 64>>>(Wq, Aq, bq, 0);
    fold_kernel<<<dim3(512, 8), 64>>>(Wk, Ak, bk, 1);
    gemm_qkv_kernel<<<dim3(8, 16, 3), 256>>>(query, key_, value, Wv, bv);
    attn_kernel<<<dim3(Sd / TQ, Hd, Bd), 256>>>(av, attn_out);
    gemm_out_kernel<<<dim3(8, 16), 256>>>(Wo, bo, out);
}